// round 14
// baseline (speedup 1.0000x reference)
#include <cuda_runtime.h>
#include <cuda_fp16.h>
#include <math.h>
#include <stdint.h>

#define B_  64
#define S_  256
#define H_  768
#define T_  13
#define D_  64
#define NEGC 1000000000000.0f

#define M1 (B_*S_)      // 16384
#define N1 (T_*2*D_)    // 1664
#define K1 H_           // 768

// ------------------------- device scratch (no allocs) ----------------------
// X packed: [batch][kblock][256 rows x 64 k] f16, swizzle pre-applied, 32KB tiles
__device__ __align__(128) half g_xp[(size_t)B_ * 12 * 256 * 64];
// W^T packed: [head][kblock][128 rows x 64 k] f16, swizzled, 16KB tiles
__device__ __align__(128) half g_wp[(size_t)T_ * 12 * 128 * 64];
__device__ float g_cos[S_ * (D_/2)];
__device__ float g_sin[S_ * (D_/2)];

// ------------------------------ PTX helpers --------------------------------
__device__ __forceinline__ uint32_t smem_u32(const void* p) {
    return (uint32_t)__cvta_generic_to_shared(p);
}
__device__ __forceinline__ void ldm_x4(uint32_t addr,
        uint32_t& r0, uint32_t& r1, uint32_t& r2, uint32_t& r3) {
    asm volatile("ldmatrix.sync.aligned.m8n8.x4.shared.b16 {%0,%1,%2,%3}, [%4];\n"
        : "=r"(r0), "=r"(r1), "=r"(r2), "=r"(r3) : "r"(addr));
}
// f16 x f16 -> f16 accumulate (2 regs = 4 halves)
__device__ __forceinline__ void mma_h(uint32_t& c0, uint32_t& c1,
        uint32_t a0, uint32_t a1, uint32_t a2, uint32_t a3,
        uint32_t b0, uint32_t b1) {
    asm volatile(
        "mma.sync.aligned.m16n8k16.row.col.f16.f16.f16.f16 "
        "{%0,%1}, {%2,%3,%4,%5}, {%6,%7}, {%0,%1};\n"
        : "+r"(c0), "+r"(c1)
        : "r"(a0), "r"(a1), "r"(a2), "r"(a3), "r"(b0), "r"(b1));
}
#define MBAR_INIT(addr, cnt) \
    asm volatile("mbarrier.init.shared.b64 [%0], %1;" \
        :: "r"((uint32_t)(addr)), "r"((uint32_t)(cnt)) : "memory")
#define MBAR_EXPECT(addr, tx) \
    asm volatile("mbarrier.arrive.expect_tx.shared.b64 _, [%0], %1;" \
        :: "r"((uint32_t)(addr)), "r"((uint32_t)(tx)) : "memory")
#define MBAR_ARRIVE(addr) \
    asm volatile("mbarrier.arrive.shared.b64 _, [%0];" \
        :: "r"((uint32_t)(addr)) : "memory")
#define MBAR_WAIT(addr, parity) do { \
    uint32_t _m = (uint32_t)(addr); uint32_t _p = (uint32_t)(parity); uint32_t _d; \
    asm volatile("{\n\t.reg .pred p;\n\t" \
        "mbarrier.try_wait.parity.acquire.cta.shared::cta.b64 p, [%1], %2;\n\t" \
        "selp.b32 %0, 1, 0, p;\n\t}" : "=r"(_d) : "r"(_m), "r"(_p) : "memory"); \
    if (!_d) { \
        asm volatile("{\n\t.reg .pred P1;\n\t" \
            "WL_%=:\n\t" \
            "mbarrier.try_wait.parity.acquire.cta.shared::cta.b64 P1, [%0], %1, 0x989680;\n\t" \
            "@P1 bra.uni WD_%=;\n\t" \
            "bra.uni WL_%=;\n\t" \
            "WD_%=:\n\t}" :: "r"(_m), "r"(_p) : "memory"); \
    } \
} while (0)
#define BULK_G2S(dst, src, bytes, mbar) \
    asm volatile("cp.async.bulk.shared::cluster.global.mbarrier::complete_tx::bytes " \
        "[%0], [%1], %2, [%3];\n" \
        :: "r"((uint32_t)(dst)), "l"(src), "r"((uint32_t)(bytes)), \
           "r"((uint32_t)(mbar)) : "memory")
#define FENCE_PROXY_ASYNC() \
    asm volatile("fence.proxy.async.shared::cta;" ::: "memory")

// ---------------------------------------------------------------------------
// Prep: X fp32 -> packed swizzled f16 tiles, W -> packed swizzled W^T f16
// tiles, RoPE table. blocks [0,12288): X | [12288,13536): W | rest: rope
// ---------------------------------------------------------------------------
__global__ __launch_bounds__(256) void prep_kernel(
    const float* __restrict__ X, const float* __restrict__ W)
{
    const int bx  = blockIdx.x;
    const int tid = threadIdx.x;

    if (bx < 12288) {                       // X: one float4 (4 k-elems) each
        int i = bx * 256 + tid;             // [0, 3145728)
        float4 v = reinterpret_cast<const float4*>(X)[i];
        int row = i / 192;                  // global row 0..16383
        int k   = (i % 192) * 4;            // k offset, multiple of 4
        int bb  = row >> 8, r = row & 255;
        int kb  = k >> 6, c = k & 63;
        size_t dst = (((size_t)bb * 12 + kb) << 14)
                   + (r << 6) + (((c >> 3) ^ (r & 7)) << 3) + (c & 7);
        half2 h0 = __floats2half2_rn(v.x, v.y);
        half2 h1 = __floats2half2_rn(v.z, v.w);
        uint2 pack = make_uint2(*reinterpret_cast<uint32_t*>(&h0),
                                *reinterpret_cast<uint32_t*>(&h1));
        *reinterpret_cast<uint2*>(&g_xp[dst]) = pack;
    } else if (bx < 13536) {                // W [768,1664] -> packed W^T tiles
        __shared__ float t[32][33];
        int bw = bx - 12288;
        int x0 = (bw % 52) * 32;            // n
        int y0 = (bw / 52) * 32;            // k
        int tx = tid & 31, ty = tid >> 5;
        #pragma unroll
        for (int i = 0; i < 4; i++)
            t[ty + i*8][tx] = W[(size_t)(y0 + ty + i*8) * N1 + x0 + tx];
        __syncthreads();
        #pragma unroll
        for (int i = 0; i < 4; i++) {
            int n = x0 + ty + i*8;
            int k = y0 + tx;
            int head = n >> 7, nl = n & 127;
            int kb = k >> 6, c = k & 63;
            size_t dst = (((size_t)head * 12 + kb) << 13)
                       + (nl << 6) + (((c >> 3) ^ (nl & 7)) << 3) + (c & 7);
            g_wp[dst] = __float2half(t[tx][ty + i*8]);
        }
    } else {                                 // RoPE table (fp64)
        int idx = (bx - 13536) * 256 + tid;
        if (idx < S_ * (D_/2)) {
            int s = idx >> 5;
            int i = idx & 31;
            double inv = pow(10000.0, -2.0 * (double)i / (double)D_);
            double ang = (double)s * inv;
            g_cos[idx] = (float)cos(ang);
            g_sin[idx] = (float)sin(ang);
        }
    }
}

// ---------------------------------------------------------------------------
// Fused kernel: one CTA per (batch, head), 256 threads, 2 CTAs/SM.
//   Stage 1: C[256,128] = X_b @ Wh (K=768), f16 mma, cp.async.bulk double buf
//            (mbarrier producer/consumer), ki rotation, B-fragment software
//            pipelining (B(njp+1) in flight during HMMAs of njp).
//   Stage 2: bias + RoPE -> q,k f16 tiles in smem.
//   Stage 3: logits = q k^T; all causally-dead warp tiles (wm>wn, pass 0)
//            skipped with coalesced const stores; B pipelined likewise.
// ---------------------------------------------------------------------------
__global__ __launch_bounds__(256, 2) void fused_gp_kernel(
    const float* __restrict__ bias, const float* __restrict__ attn_mask,
    float* __restrict__ out)
{
    extern __shared__ __align__(16) char dyn[];
    __shared__ float s_bias[128];
    __shared__ float pads[256];
    __shared__ __align__(8) uint64_t s_full[2];
    __shared__ __align__(8) uint64_t s_cons[2];

    char* base = (char*)(((uintptr_t)dyn + 1023) & ~(uintptr_t)1023);
    half* smA = (half*)base;                 // 2 bufs x 256x64 = 64KB
    half* smB = (half*)(base + 65536);       // 2 bufs x 128x64 = 32KB

    const int tid  = threadIdx.x;
    const int lane = tid & 31;
    const int warp = tid >> 5;
    const int wm   = warp & 3;     // M: 4 x 64 rows
    const int wn   = warp >> 2;    // N: 2 x 64 cols
    const int krot = warp & 3;     // per-warp k-chunk rotation
    const int h    = blockIdx.x;   // head
    const int bb   = blockIdx.y;   // batch

    if (tid == 0) {
        MBAR_INIT(smem_u32(&s_full[0]), 1);
        MBAR_INIT(smem_u32(&s_full[1]), 1);
        MBAR_INIT(smem_u32(&s_cons[0]), 8);
        MBAR_INIT(smem_u32(&s_cons[1]), 8);
    }
    if (tid < 128) s_bias[tid] = bias[h * 128 + tid];
    pads[tid] = attn_mask[bb * 256 + tid];
    __syncthreads();

    auto issue = [&](int buf, int kb) {
        FENCE_PROXY_ASYNC();
        uint32_t mb = smem_u32(&s_full[buf]);
        MBAR_EXPECT(mb, 49152);
        BULK_G2S(smem_u32(smA + buf * 16384),
                 g_xp + (((size_t)bb * 12 + kb) << 14), 32768, mb);
        BULK_G2S(smem_u32(smB + buf * 8192),
                 g_wp + (((size_t)h * 12 + kb) << 13), 16384, mb);
    };

    if (tid == 0) issue(0, 0);

    // f16x2 accumulators [mi][nj][hh]: 64 registers
    uint32_t acc[4][8][2];
    #pragma unroll
    for (int i = 0; i < 4; i++)
        #pragma unroll
        for (int j = 0; j < 8; j++) { acc[i][j][0] = 0u; acc[i][j][1] = 0u; }

    // ---------------- Stage 1 mainloop: 12 x BK=64 --------------------------
    for (int it = 0; it < 12; it++) {
        const int b = it & 1;
        if (it < 11 && tid == 0) {
            const int nb = (it + 1) & 1;
            const int u  = (it + 1) >> 1;          // use index of buffer nb
            if (u >= 1) MBAR_WAIT(smem_u32(&s_cons[nb]), (u - 1) & 1);
            issue(nb, it + 1);
        }
        MBAR_WAIT(smem_u32(&s_full[b]), (it >> 1) & 1);

        const half* A  = smA + b * 16384;
        const half* Bs = smB + b * 8192;

        #pragma unroll
        for (int ki0 = 0; ki0 < 4; ki0++) {
            const int ki = (ki0 + krot) & 3;       // de-phased k-chunk order
            uint32_t a[4][4];
            #pragma unroll
            for (int mi = 0; mi < 4; mi++) {
                int row = wm * 64 + mi * 16 + (lane & 15);
                int kch = ki * 2 + (lane >> 4);
                ldm_x4(smem_u32(A + row * 64 + ((kch ^ (row & 7)) << 3)),
                       a[mi][0], a[mi][1], a[mi][2], a[mi][3]);
            }
            // B-fragment software pipeline: bc = current, bn = next
            const int mat  = lane >> 3;
            const int brow0 = wn * 64 + ((mat >> 1) << 3) + (lane & 7);
            const int kchB  = ki * 2 + (mat & 1);
            uint32_t bc0, bc1, bc2, bc3;
            {
                int rowb = brow0;
                ldm_x4(smem_u32(Bs + rowb * 64 + ((kchB ^ (rowb & 7)) << 3)),
                       bc0, bc1, bc2, bc3);
            }
            #pragma unroll
            for (int njp = 0; njp < 4; njp++) {
                uint32_t bn0, bn1, bn2, bn3;
                if (njp < 3) {
                    int rowb = brow0 + (njp + 1) * 16;
                    ldm_x4(smem_u32(Bs + rowb * 64 + ((kchB ^ (rowb & 7)) << 3)),
                           bn0, bn1, bn2, bn3);
                }
                #pragma unroll
                for (int mi = 0; mi < 4; mi++) {
                    mma_h(acc[mi][njp*2][0],   acc[mi][njp*2][1],
                          a[mi][0], a[mi][1], a[mi][2], a[mi][3], bc0, bc1);
                    mma_h(acc[mi][njp*2+1][0], acc[mi][njp*2+1][1],
                          a[mi][0], a[mi][1], a[mi][2], a[mi][3], bc2, bc3);
                }
                if (njp < 3) { bc0 = bn0; bc1 = bn1; bc2 = bn2; bc3 = bn3; }
            }
        }
        __syncwarp();
        if (lane == 0) MBAR_ARRIVE(smem_u32(&s_cons[b]));   // buffer consumed
    }
    __syncthreads();   // all warps done with smA/smB before overwriting

    // ---------------- Stage 2: bias + RoPE -> q/k f16 smem ------------------
    half* Qs = (half*)base;                    // 256 x 64 = 32KB
    half* Ks = (half*)(base + 32768);          // 256 x 64 = 32KB
    #pragma unroll
    for (int mi = 0; mi < 4; mi++) {
        #pragma unroll
        for (int nj = 0; nj < 8; nj++) {
            int col = wn * 64 + nj * 8 + ((lane & 3) << 1);   // 0..127 even
            int d   = col & 63;
            half* dst = (col < 64) ? Qs : Ks;
            float bx = s_bias[col];
            float by = s_bias[col + 1];
            int pi    = d >> 1;
            int chunk = d >> 3;
            int dlo   = d & 7;
            #pragma unroll
            for (int hh = 0; hh < 2; hh++) {
                int srow = wm * 64 + mi * 16 + (lane >> 2) + hh * 8;
                float2 xy = __half22float2(
                    *reinterpret_cast<half2*>(&acc[mi][nj][hh]));
                float x = xy.x + bx;
                float y = xy.y + by;
                float cs = g_cos[srow * 32 + pi];
                float sn = g_sin[srow * 32 + pi];
                *reinterpret_cast<half2*>(
                    &dst[srow * 64 + ((chunk ^ (srow & 7)) << 3) + dlo]) =
                    __floats2half2_rn(x * cs - y * sn, y * cs + x * sn);
            }
        }
    }
    __syncthreads();

    // ---------------- Stage 3: logits = q @ k^T, 2 passes -------------------
    const size_t zbase = ((size_t)(bb * T_ + h)) << 16;   // *65536
    #pragma unroll
    for (int pass = 0; pass < 2; pass++) {
        // pass 0: tile fully causally masked iff wm > wn
        // (min m = 64*wm > max n = 64*wn + 63)
        const bool skip = (pass == 0) && (wm > wn);

        if (skip) {
            // constant per column; fully-coalesced stg.128 (2 rows/instr)
            int n4 = wn * 64 + (lane & 15) * 4;
            float4 v = make_float4(
                (-(1.0f - pads[n4])     * NEGC - NEGC) * 0.125f,
                (-(1.0f - pads[n4 + 1]) * NEGC - NEGC) * 0.125f,
                (-(1.0f - pads[n4 + 2]) * NEGC - NEGC) * 0.125f,
                (-(1.0f - pads[n4 + 3]) * NEGC - NEGC) * 0.125f);
            #pragma unroll
            for (int i = 0; i < 32; i++) {
                int m = wm * 64 + i * 2 + (lane >> 4);
                *reinterpret_cast<float4*>(
                    &out[zbase + (size_t)m * 256 + n4]) = v;
            }
            continue;
        }

        #pragma unroll
        for (int i = 0; i < 4; i++)
            #pragma unroll
            for (int j = 0; j < 8; j++) { acc[i][j][0] = 0u; acc[i][j][1] = 0u; }

        #pragma unroll
        for (int ki0 = 0; ki0 < 4; ki0++) {
            const int ki = (ki0 + krot) & 3;
            uint32_t a[4][4];
            #pragma unroll
            for (int mi = 0; mi < 4; mi++) {
                int row = wm * 64 + mi * 16 + (lane & 15);
                int kch = ki * 2 + (lane >> 4);
                ldm_x4(smem_u32(Qs + row * 64 + ((kch ^ (row & 7)) << 3)),
                       a[mi][0], a[mi][1], a[mi][2], a[mi][3]);
            }
            const int mat   = lane >> 3;
            const int brow0 = pass * 128 + wn * 64 + ((mat >> 1) << 3) + (lane & 7);
            const int kchB  = ki * 2 + (mat & 1);
            uint32_t bc0, bc1, bc2, bc3;
            {
                int rowb = brow0;
                ldm_x4(smem_u32(Ks + rowb * 64 + ((kchB ^ (rowb & 7)) << 3)),
                       bc0, bc1, bc2, bc3);
            }
            #pragma unroll
            for (int njp = 0; njp < 4; njp++) {
                uint32_t bn0, bn1, bn2, bn3;
                if (njp < 3) {
                    int rowb = brow0 + (njp + 1) * 16;
                    ldm_x4(smem_u32(Ks + rowb * 64 + ((kchB ^ (rowb & 7)) << 3)),
                           bn0, bn1, bn2, bn3);
                }
                #pragma unroll
                for (int mi = 0; mi < 4; mi++) {
                    mma_h(acc[mi][njp*2][0],   acc[mi][njp*2][1],
                          a[mi][0], a[mi][1], a[mi][2], a[mi][3], bc0, bc1);
                    mma_h(acc[mi][njp*2+1][0], acc[mi][njp*2+1][1],
                          a[mi][0], a[mi][1], a[mi][2], a[mi][3], bc2, bc3);
                }
                if (njp < 3) { bc0 = bn0; bc1 = bn1; bc2 = bn2; bc3 = bn3; }
            }
        }

        // epilogue: pad + strict-lower causal + scale, direct float2 stores
        #pragma unroll
        for (int mi = 0; mi < 4; mi++) {
            #pragma unroll
            for (int nj = 0; nj < 8; nj++) {
                int n  = pass * 128 + wn * 64 + nj * 8 + ((lane & 3) << 1);
                float p0 = pads[n];
                float p1 = pads[n + 1];
                #pragma unroll
                for (int hh = 0; hh < 2; hh++) {
                    int m = wm * 64 + mi * 16 + (lane >> 2) + hh * 8;
                    float2 xy = __half22float2(
                        *reinterpret_cast<half2*>(&acc[mi][nj][hh]));
                    float t0 = xy.x * p0 - (1.0f - p0) * NEGC;
                    float t1 = xy.y * p1 - (1.0f - p1) * NEGC;
                    if (m > n)     t0 -= NEGC;
                    if (m > n + 1) t1 -= NEGC;
                    float2 v = make_float2(t0 * 0.125f, t1 * 0.125f);
                    *reinterpret_cast<float2*>(
                        &out[zbase + (size_t)m * 256 + n]) = v;
                }
            }
        }
    }
}

// ---------------------------------------------------------------------------
extern "C" void kernel_launch(void* const* d_in, const int* in_sizes, int n_in,
                              void* d_out, int out_size) {
    const float* X    = (const float*)d_in[0];   // [B,S,H]
    const float* W    = (const float*)d_in[1];   // [H, T*2*D]
    const float* bias = (const float*)d_in[2];   // [T*2*D]
    const float* mask = (const float*)d_in[3];   // [B,S]
    float* out = (float*)d_out;                  // [B,T,S,S]

    prep_kernel<<<13568, 256>>>(X, W);

    cudaFuncSetAttribute(fused_gp_kernel,
                         cudaFuncAttributeMaxDynamicSharedMemorySize, 99328);
    fused_gp_kernel<<<dim3(13, 64), 256, 99328>>>(bias, mask, out);
}

// round 15
// speedup vs baseline: 1.0420x; 1.0420x over previous
#include <cuda_runtime.h>
#include <cuda_fp16.h>
#include <math.h>
#include <stdint.h>

#define B_  64
#define S_  256
#define H_  768
#define T_  13
#define D_  64
#define NEGC 1000000000000.0f

#define M1 (B_*S_)      // 16384
#define N1 (T_*2*D_)    // 1664
#define K1 H_           // 768

// ------------------------- device scratch (no allocs) ----------------------
// X packed: [batch][kblock][256 rows x 64 k] f16, swizzle pre-applied, 32KB tiles
__device__ __align__(128) half g_xp[(size_t)B_ * 12 * 256 * 64];
// W^T packed: [head][kblock][128 rows x 64 k] f16, swizzled, 16KB tiles
__device__ __align__(128) half g_wp[(size_t)T_ * 12 * 128 * 64];
__device__ float g_cos[S_ * (D_/2)];
__device__ float g_sin[S_ * (D_/2)];

// ------------------------------ PTX helpers --------------------------------
__device__ __forceinline__ uint32_t smem_u32(const void* p) {
    return (uint32_t)__cvta_generic_to_shared(p);
}
__device__ __forceinline__ void ldm_x4(uint32_t addr,
        uint32_t& r0, uint32_t& r1, uint32_t& r2, uint32_t& r3) {
    asm volatile("ldmatrix.sync.aligned.m8n8.x4.shared.b16 {%0,%1,%2,%3}, [%4];\n"
        : "=r"(r0), "=r"(r1), "=r"(r2), "=r"(r3) : "r"(addr));
}
// f16 x f16 -> f16 accumulate (2 regs = 4 halves)
__device__ __forceinline__ void mma_h(uint32_t& c0, uint32_t& c1,
        uint32_t a0, uint32_t a1, uint32_t a2, uint32_t a3,
        uint32_t b0, uint32_t b1) {
    asm volatile(
        "mma.sync.aligned.m16n8k16.row.col.f16.f16.f16.f16 "
        "{%0,%1}, {%2,%3,%4,%5}, {%6,%7}, {%0,%1};\n"
        : "+r"(c0), "+r"(c1)
        : "r"(a0), "r"(a1), "r"(a2), "r"(a3), "r"(b0), "r"(b1));
}
#define MBAR_INIT(addr, cnt) \
    asm volatile("mbarrier.init.shared.b64 [%0], %1;" \
        :: "r"((uint32_t)(addr)), "r"((uint32_t)(cnt)) : "memory")
#define MBAR_EXPECT(addr, tx) \
    asm volatile("mbarrier.arrive.expect_tx.shared.b64 _, [%0], %1;" \
        :: "r"((uint32_t)(addr)), "r"((uint32_t)(tx)) : "memory")
#define MBAR_ARRIVE(addr) \
    asm volatile("mbarrier.arrive.shared.b64 _, [%0];" \
        :: "r"((uint32_t)(addr)) : "memory")
#define MBAR_WAIT(addr, parity) do { \
    uint32_t _m = (uint32_t)(addr); uint32_t _p = (uint32_t)(parity); uint32_t _d; \
    asm volatile("{\n\t.reg .pred p;\n\t" \
        "mbarrier.try_wait.parity.acquire.cta.shared::cta.b64 p, [%1], %2;\n\t" \
        "selp.b32 %0, 1, 0, p;\n\t}" : "=r"(_d) : "r"(_m), "r"(_p) : "memory"); \
    if (!_d) { \
        asm volatile("{\n\t.reg .pred P1;\n\t" \
            "WL_%=:\n\t" \
            "mbarrier.try_wait.parity.acquire.cta.shared::cta.b64 P1, [%0], %1, 0x989680;\n\t" \
            "@P1 bra.uni WD_%=;\n\t" \
            "bra.uni WL_%=;\n\t" \
            "WD_%=:\n\t}" :: "r"(_m), "r"(_p) : "memory"); \
    } \
} while (0)
#define BULK_G2S(dst, src, bytes, mbar) \
    asm volatile("cp.async.bulk.shared::cluster.global.mbarrier::complete_tx::bytes " \
        "[%0], [%1], %2, [%3];\n" \
        :: "r"((uint32_t)(dst)), "l"(src), "r"((uint32_t)(bytes)), \
           "r"((uint32_t)(mbar)) : "memory")
#define FENCE_PROXY_ASYNC() \
    asm volatile("fence.proxy.async.shared::cta;" ::: "memory")

// ---------------------------------------------------------------------------
// Prep: X fp32 -> packed swizzled f16 tiles, W -> packed swizzled W^T f16
// tiles, RoPE table. blocks [0,12288): X | [12288,13536): W | rest: rope
// ---------------------------------------------------------------------------
__global__ __launch_bounds__(256) void prep_kernel(
    const float* __restrict__ X, const float* __restrict__ W)
{
    const int bx  = blockIdx.x;
    const int tid = threadIdx.x;

    if (bx < 12288) {                       // X: one float4 (4 k-elems) each
        int i = bx * 256 + tid;             // [0, 3145728)
        float4 v = reinterpret_cast<const float4*>(X)[i];
        int row = i / 192;                  // global row 0..16383
        int k   = (i % 192) * 4;            // k offset, multiple of 4
        int bb  = row >> 8, r = row & 255;
        int kb  = k >> 6, c = k & 63;
        size_t dst = (((size_t)bb * 12 + kb) << 14)
                   + (r << 6) + (((c >> 3) ^ (r & 7)) << 3) + (c & 7);
        half2 h0 = __floats2half2_rn(v.x, v.y);
        half2 h1 = __floats2half2_rn(v.z, v.w);
        uint2 pack = make_uint2(*reinterpret_cast<uint32_t*>(&h0),
                                *reinterpret_cast<uint32_t*>(&h1));
        *reinterpret_cast<uint2*>(&g_xp[dst]) = pack;
    } else if (bx < 13536) {                // W [768,1664] -> packed W^T tiles
        __shared__ float t[32][33];
        int bw = bx - 12288;
        int x0 = (bw % 52) * 32;            // n
        int y0 = (bw / 52) * 32;            // k
        int tx = tid & 31, ty = tid >> 5;
        #pragma unroll
        for (int i = 0; i < 4; i++)
            t[ty + i*8][tx] = W[(size_t)(y0 + ty + i*8) * N1 + x0 + tx];
        __syncthreads();
        #pragma unroll
        for (int i = 0; i < 4; i++) {
            int n = x0 + ty + i*8;
            int k = y0 + tx;
            int head = n >> 7, nl = n & 127;
            int kb = k >> 6, c = k & 63;
            size_t dst = (((size_t)head * 12 + kb) << 13)
                       + (nl << 6) + (((c >> 3) ^ (nl & 7)) << 3) + (c & 7);
            g_wp[dst] = __float2half(t[tx][ty + i*8]);
        }
    } else {                                 // RoPE table (fp64)
        int idx = (bx - 13536) * 256 + tid;
        if (idx < S_ * (D_/2)) {
            int s = idx >> 5;
            int i = idx & 31;
            double inv = pow(10000.0, -2.0 * (double)i / (double)D_);
            double ang = (double)s * inv;
            g_cos[idx] = (float)cos(ang);
            g_sin[idx] = (float)sin(ang);
        }
    }
}

// ---------------------------------------------------------------------------
// Fused kernel: one CTA per (batch, head), 256 threads, 2 CTAs/SM.
//   Stage 1: C[256,128] = X_b @ Wh (K=768), f16 mma, cp.async.bulk double buf
//            (mbarrier producer/consumer), per-warp ki rotation.
//   Stage 2: bias + RoPE -> q,k f16 tiles in smem.
//   Stage 3: logits = q k^T; all causally-dead warp tiles (pass 0, wm>wn)
//            skipped with coalesced constant stores.
// ---------------------------------------------------------------------------
__global__ __launch_bounds__(256, 2) void fused_gp_kernel(
    const float* __restrict__ bias, const float* __restrict__ attn_mask,
    float* __restrict__ out)
{
    extern __shared__ __align__(16) char dyn[];
    __shared__ float s_bias[128];
    __shared__ float pads[256];
    __shared__ __align__(8) uint64_t s_full[2];
    __shared__ __align__(8) uint64_t s_cons[2];

    char* base = (char*)(((uintptr_t)dyn + 1023) & ~(uintptr_t)1023);
    half* smA = (half*)base;                 // 2 bufs x 256x64 = 64KB
    half* smB = (half*)(base + 65536);       // 2 bufs x 128x64 = 32KB

    const int tid  = threadIdx.x;
    const int lane = tid & 31;
    const int warp = tid >> 5;
    const int wm   = warp & 3;     // M: 4 x 64 rows
    const int wn   = warp >> 2;    // N: 2 x 64 cols
    const int krot = warp & 3;     // per-warp k-chunk rotation
    const int h    = blockIdx.x;   // head
    const int bb   = blockIdx.y;   // batch

    auto issue = [&](int buf, int kb) {
        FENCE_PROXY_ASYNC();
        uint32_t mb = smem_u32(&s_full[buf]);
        MBAR_EXPECT(mb, 49152);
        BULK_G2S(smem_u32(smA + buf * 16384),
                 g_xp + (((size_t)bb * 12 + kb) << 14), 32768, mb);
        BULK_G2S(smem_u32(smB + buf * 8192),
                 g_wp + (((size_t)h * 12 + kb) << 13), 16384, mb);
    };

    // Early issue: tid0 inits barriers and launches the first copy BEFORE the
    // block-wide setup loads; program order makes init->copy safe for tid0,
    // and all consumers pass __syncthreads below before waiting on s_full.
    if (tid == 0) {
        MBAR_INIT(smem_u32(&s_full[0]), 1);
        MBAR_INIT(smem_u32(&s_full[1]), 1);
        MBAR_INIT(smem_u32(&s_cons[0]), 8);
        MBAR_INIT(smem_u32(&s_cons[1]), 8);
        issue(0, 0);
    }
    if (tid < 128) s_bias[tid] = bias[h * 128 + tid];
    pads[tid] = attn_mask[bb * 256 + tid];
    __syncthreads();

    // f16x2 accumulators [mi][nj][hh]: 64 registers
    uint32_t acc[4][8][2];
    #pragma unroll
    for (int i = 0; i < 4; i++)
        #pragma unroll
        for (int j = 0; j < 8; j++) { acc[i][j][0] = 0u; acc[i][j][1] = 0u; }

    // ---------------- Stage 1 mainloop: 12 x BK=64 --------------------------
    for (int it = 0; it < 12; it++) {
        const int b = it & 1;
        if (it < 11 && tid == 0) {
            const int nb = (it + 1) & 1;
            const int u  = (it + 1) >> 1;          // use index of buffer nb
            if (u >= 1) MBAR_WAIT(smem_u32(&s_cons[nb]), (u - 1) & 1);
            issue(nb, it + 1);
        }
        MBAR_WAIT(smem_u32(&s_full[b]), (it >> 1) & 1);

        const half* A  = smA + b * 16384;
        const half* Bs = smB + b * 8192;
        #pragma unroll
        for (int ki0 = 0; ki0 < 4; ki0++) {
            const int ki = (ki0 + krot) & 3;       // de-phased k-chunk order
            uint32_t a[4][4];
            #pragma unroll
            for (int mi = 0; mi < 4; mi++) {
                int row = wm * 64 + mi * 16 + (lane & 15);
                int kch = ki * 2 + (lane >> 4);
                ldm_x4(smem_u32(A + row * 64 + ((kch ^ (row & 7)) << 3)),
                       a[mi][0], a[mi][1], a[mi][2], a[mi][3]);
            }
            #pragma unroll
            for (int njp = 0; njp < 4; njp++) {
                int mat  = lane >> 3;
                int rowb = wn * 64 + njp * 16 + ((mat >> 1) << 3) + (lane & 7);
                int kch  = ki * 2 + (mat & 1);
                uint32_t b0, b1, b2, b3;
                ldm_x4(smem_u32(Bs + rowb * 64 + ((kch ^ (rowb & 7)) << 3)),
                       b0, b1, b2, b3);
                #pragma unroll
                for (int mi = 0; mi < 4; mi++) {
                    mma_h(acc[mi][njp*2][0],   acc[mi][njp*2][1],
                          a[mi][0], a[mi][1], a[mi][2], a[mi][3], b0, b1);
                    mma_h(acc[mi][njp*2+1][0], acc[mi][njp*2+1][1],
                          a[mi][0], a[mi][1], a[mi][2], a[mi][3], b2, b3);
                }
            }
        }
        __syncwarp();
        if (lane == 0) MBAR_ARRIVE(smem_u32(&s_cons[b]));   // buffer consumed
    }
    __syncthreads();   // all warps done with smA/smB before overwriting

    // ---------------- Stage 2: bias + RoPE -> q/k f16 smem ------------------
    half* Qs = (half*)base;                    // 256 x 64 = 32KB
    half* Ks = (half*)(base + 32768);          // 256 x 64 = 32KB
    #pragma unroll
    for (int mi = 0; mi < 4; mi++) {
        #pragma unroll
        for (int nj = 0; nj < 8; nj++) {
            int col = wn * 64 + nj * 8 + ((lane & 3) << 1);   // 0..127 even
            int d   = col & 63;
            half* dst = (col < 64) ? Qs : Ks;
            float bx = s_bias[col];
            float by = s_bias[col + 1];
            int pi    = d >> 1;
            int chunk = d >> 3;
            int dlo   = d & 7;
            #pragma unroll
            for (int hh = 0; hh < 2; hh++) {
                int srow = wm * 64 + mi * 16 + (lane >> 2) + hh * 8;
                float2 xy = __half22float2(
                    *reinterpret_cast<half2*>(&acc[mi][nj][hh]));
                float x = xy.x + bx;
                float y = xy.y + by;
                float cs = g_cos[srow * 32 + pi];
                float sn = g_sin[srow * 32 + pi];
                *reinterpret_cast<half2*>(
                    &dst[srow * 64 + ((chunk ^ (srow & 7)) << 3) + dlo]) =
                    __floats2half2_rn(x * cs - y * sn, y * cs + x * sn);
            }
        }
    }
    __syncthreads();

    // ---------------- Stage 3: logits = q @ k^T, 2 passes -------------------
    const size_t zbase = ((size_t)(bb * T_ + h)) << 16;   // *65536
    #pragma unroll
    for (int pass = 0; pass < 2; pass++) {
        // pass 0: tile fully causally masked iff wm > wn
        // (min m = 64*wm > max n = 64*wn + 63)
        const bool skip = (pass == 0) && (wm > wn);

        if (skip) {
            // constant per column; fully-coalesced stg.128 (2 rows/instr)
            int n4 = wn * 64 + (lane & 15) * 4;
            float4 v = make_float4(
                (-(1.0f - pads[n4])     * NEGC - NEGC) * 0.125f,
                (-(1.0f - pads[n4 + 1]) * NEGC - NEGC) * 0.125f,
                (-(1.0f - pads[n4 + 2]) * NEGC - NEGC) * 0.125f,
                (-(1.0f - pads[n4 + 3]) * NEGC - NEGC) * 0.125f);
            #pragma unroll
            for (int i = 0; i < 32; i++) {
                int m = wm * 64 + i * 2 + (lane >> 4);
                *reinterpret_cast<float4*>(
                    &out[zbase + (size_t)m * 256 + n4]) = v;
            }
            continue;
        }

        #pragma unroll
        for (int i = 0; i < 4; i++)
            #pragma unroll
            for (int j = 0; j < 8; j++) { acc[i][j][0] = 0u; acc[i][j][1] = 0u; }

        #pragma unroll
        for (int ki0 = 0; ki0 < 4; ki0++) {
            const int ki = (ki0 + krot) & 3;
            uint32_t a[4][4];
            #pragma unroll
            for (int mi = 0; mi < 4; mi++) {
                int row = wm * 64 + mi * 16 + (lane & 15);
                int kch = ki * 2 + (lane >> 4);
                ldm_x4(smem_u32(Qs + row * 64 + ((kch ^ (row & 7)) << 3)),
                       a[mi][0], a[mi][1], a[mi][2], a[mi][3]);
            }
            #pragma unroll
            for (int njp = 0; njp < 4; njp++) {
                int mat  = lane >> 3;
                int rowb = pass * 128 + wn * 64 + njp * 16
                         + ((mat >> 1) << 3) + (lane & 7);
                int kch  = ki * 2 + (mat & 1);
                uint32_t b0, b1, b2, b3;
                ldm_x4(smem_u32(Ks + rowb * 64 + ((kch ^ (rowb & 7)) << 3)),
                       b0, b1, b2, b3);
                #pragma unroll
                for (int mi = 0; mi < 4; mi++) {
                    mma_h(acc[mi][njp*2][0],   acc[mi][njp*2][1],
                          a[mi][0], a[mi][1], a[mi][2], a[mi][3], b0, b1);
                    mma_h(acc[mi][njp*2+1][0], acc[mi][njp*2+1][1],
                          a[mi][0], a[mi][1], a[mi][2], a[mi][3], b2, b3);
                }
            }
        }

        // epilogue: pad + strict-lower causal + scale, direct float2 stores
        #pragma unroll
        for (int mi = 0; mi < 4; mi++) {
            #pragma unroll
            for (int nj = 0; nj < 8; nj++) {
                int n  = pass * 128 + wn * 64 + nj * 8 + ((lane & 3) << 1);
                float p0 = pads[n];
                float p1 = pads[n + 1];
                #pragma unroll
                for (int hh = 0; hh < 2; hh++) {
                    int m = wm * 64 + mi * 16 + (lane >> 2) + hh * 8;
                    float2 xy = __half22float2(
                        *reinterpret_cast<half2*>(&acc[mi][nj][hh]));
                    float t0 = xy.x * p0 - (1.0f - p0) * NEGC;
                    float t1 = xy.y * p1 - (1.0f - p1) * NEGC;
                    if (m > n)     t0 -= NEGC;
                    if (m > n + 1) t1 -= NEGC;
                    float2 v = make_float2(t0 * 0.125f, t1 * 0.125f);
                    *reinterpret_cast<float2*>(
                        &out[zbase + (size_t)m * 256 + n]) = v;
                }
            }
        }
    }
}

// ---------------------------------------------------------------------------
extern "C" void kernel_launch(void* const* d_in, const int* in_sizes, int n_in,
                              void* d_out, int out_size) {
    const float* X    = (const float*)d_in[0];   // [B,S,H]
    const float* W    = (const float*)d_in[1];   // [H, T*2*D]
    const float* bias = (const float*)d_in[2];   // [T*2*D]
    const float* mask = (const float*)d_in[3];   // [B,S]
    float* out = (float*)d_out;                  // [B,T,S,S]

    prep_kernel<<<13568, 256>>>(X, W);

    cudaFuncSetAttribute(fused_gp_kernel,
                         cudaFuncAttributeMaxDynamicSharedMemorySize, 99328);
    fused_gp_kernel<<<dim3(13, 64), 256, 99328>>>(bias, mask, out);
}